// round 3
// baseline (speedup 1.0000x reference)
#include <cuda_runtime.h>
#include <cuda_bf16.h>
#include <cstdint>

// Problem constants
static constexpr int BQ  = 2;
static constexpr int NN  = 2048;
static constexpr int FF  = 64;
static constexpr int HH  = 4;
static constexpr int HID = 128;
static constexpr int HIN = 128;   // H*C

// packed fp32x2 FMA (sm_100+); d = a*b + d lanewise on {lo,hi}
#define FMA2(d, a, b) asm("fma.rn.f32x2 %0, %1, %2, %0;" : "+l"(d) : "l"(a), "l"(b))
#define UNPACK2(lo, hi, p) asm("mov.b64 {%0, %1}, %2;" : "=f"(lo), "=f"(hi) : "l"(p))

// ---------------- device scratch ----------------
__device__ float g_xp[BQ * NN * HIN];
__device__ float g_es[BQ * NN * HH];
__device__ float g_en[BQ * NN * HH];
__device__ float g_cu[BQ * NN * HIN];
__device__ float g_t [BQ * NN * HID];

// ---------------- K1: xp = x @ kernel, es/en reductions ----------------
__global__ void k1_project(const float* __restrict__ x,
                           const float* __restrict__ kern,
                           const float* __restrict__ attn_self,
                           const float* __restrict__ attn_nei) {
    __shared__ float xs[8][FF];
    const int row0 = blockIdx.x * 8;
    const int t = threadIdx.x;

    for (int i = t; i < 8 * FF; i += 128) {
        int r = i / FF, f = i % FF;
        xs[r][f] = x[(size_t)(row0 + r) * FF + f];
    }
    __syncthreads();

    const float a_s = attn_self[t];
    const float a_n = attn_nei[t];
    const int h = t >> 5, lane = t & 31;

    float acc[8];
#pragma unroll
    for (int r = 0; r < 8; r++) acc[r] = 0.f;

    for (int f = 0; f < FF; f++) {
        float w = kern[f * HIN + t];
#pragma unroll
        for (int r = 0; r < 8; r++) acc[r] += xs[r][f] * w;
    }

#pragma unroll
    for (int r = 0; r < 8; r++) {
        g_xp[(size_t)(row0 + r) * HIN + t] = acc[r];
        float ps = acc[r] * a_s;
        float pn = acc[r] * a_n;
#pragma unroll
        for (int o = 16; o > 0; o >>= 1) {
            ps += __shfl_down_sync(0xffffffffu, ps, o);
            pn += __shfl_down_sync(0xffffffffu, pn, o);
        }
        if (lane == 0) {
            g_es[(row0 + r) * HH + h] = ps;
            g_en[(row0 + r) * HH + h] = pn;
        }
    }
}

// ---------------- K2: masked softmax attention + sparse aggregation ----------------
// Masked entries underflow to exactly 0.0f in fp32, identical to dense reference.
static constexpr int MAXNBR = 512;

__global__ void k2_attention(const float* __restrict__ a,
                             const float* __restrict__ bias_gat) {
    __shared__ int   nbr[MAXNBR];
    __shared__ float wgt[HH][MAXNBR];
    __shared__ int   cnt;

    const int bi = blockIdx.x;
    const int b = bi >> 11;
    const int t = threadIdx.x;
    const int h = t >> 5, lane = t & 31;
    const int base = b * NN;

    if (t == 0) cnt = 0;
    __syncthreads();

    const float4* arow4 = reinterpret_cast<const float4*>(a + (size_t)bi * NN);
    for (int j4 = t; j4 < NN / 4; j4 += 128) {
        float4 v = arow4[j4];
        if (v.x != 0.f) { int p = atomicAdd(&cnt, 1); if (p < MAXNBR) nbr[p] = j4 * 4 + 0; }
        if (v.y != 0.f) { int p = atomicAdd(&cnt, 1); if (p < MAXNBR) nbr[p] = j4 * 4 + 1; }
        if (v.z != 0.f) { int p = atomicAdd(&cnt, 1); if (p < MAXNBR) nbr[p] = j4 * 4 + 2; }
        if (v.w != 0.f) { int p = atomicAdd(&cnt, 1); if (p < MAXNBR) nbr[p] = j4 * 4 + 3; }
    }
    __syncthreads();
    const int K = cnt < MAXNBR ? cnt : MAXNBR;

    const float esi = g_es[bi * HH + h];

    // single gather pass: compute leaky score into smem + running max
    float m = -1e30f;
    for (int k = lane; k < K; k += 32) {
        float v = esi + g_en[(base + nbr[k]) * HH + h];
        float e = v > 0.f ? v : 0.2f * v;
        wgt[h][k] = e;
        m = fmaxf(m, e);
    }
#pragma unroll
    for (int o = 16; o > 0; o >>= 1) m = fmaxf(m, __shfl_xor_sync(0xffffffffu, m, o));
    __syncwarp();

    // exp + sum from smem
    float s = 0.f;
    for (int k = lane; k < K; k += 32) {
        float w = expf(wgt[h][k] - m);
        wgt[h][k] = w;
        s += w;
    }
#pragma unroll
    for (int o = 16; o > 0; o >>= 1) s += __shfl_xor_sync(0xffffffffu, s, o);
    const float inv = 1.f / s;
    __syncwarp();

    float acc = 0.f;
    for (int k = 0; k < K; k++) {
        acc += wgt[h][k] * g_xp[(size_t)(base + nbr[k]) * HIN + t];
    }
    g_cu[(size_t)bi * HIN + t] = acc * inv + bias_gat[t];
}

// ---------------- K3: fused GRU gates + h'@R_p (512 threads, 4 rows/thread) ----------------
__global__ __launch_bounds__(512) void k3_gates(
        const float* __restrict__ h_in,
        const float* __restrict__ bu, const float* __restrict__ br,
        const float* __restrict__ bc,
        const float* __restrict__ Wu, const float* __restrict__ Wr,
        const float* __restrict__ Wc, const float* __restrict__ Rp,
        float* __restrict__ hp_out) {
    __shared__ float cu[16][HIN];
    __shared__ float hh[16][HID];
    __shared__ float rh[16][HID];

    const int row0 = blockIdx.x * 16;
    const int t = threadIdx.x;
    const int col = t & 127;
    const int r0 = (t >> 7) * 4;

    float hval[4];
#pragma unroll
    for (int r = 0; r < 4; r++) {
        cu[r0 + r][col] = g_cu[(size_t)(row0 + r0 + r) * HIN + col];
        hval[r] = h_in[(size_t)(row0 + r0 + r) * HID + col];
        hh[r0 + r][col] = hval[r];
    }
    __syncthreads();

    float accU[4], accR[4];
#pragma unroll
    for (int r = 0; r < 4; r++) { accU[r] = 0.f; accR[r] = 0.f; }

    for (int i = 0; i < HIN; i++) {
        float wu = Wu[i * HID + col];
        float wr = Wr[i * HID + col];
#pragma unroll
        for (int r = 0; r < 4; r++) {
            float z = cu[r0 + r][i];
            accU[r] += z * wu;
            accR[r] += z * wr;
        }
    }
    for (int i = 0; i < HID; i++) {
        float wu = Wu[(HIN + i) * HID + col];
        float wr = Wr[(HIN + i) * HID + col];
#pragma unroll
        for (int r = 0; r < 4; r++) {
            float z = hh[r0 + r][i];
            accU[r] += z * wu;
            accR[r] += z * wr;
        }
    }

    float uu[4];
#pragma unroll
    for (int r = 0; r < 4; r++) {
        int n = (row0 + r0 + r) & (NN - 1);
        float u  = 1.f / (1.f + expf(-(bu[n] + accU[r])));
        float rr = 1.f / (1.f + expf(-(br[n] + accR[r])));
        uu[r] = u;
        rh[r0 + r][col] = rr * hval[r];
    }
    __syncthreads();

    float accC[4];
#pragma unroll
    for (int r = 0; r < 4; r++) accC[r] = 0.f;

    for (int i = 0; i < HIN; i++) {
        float wc = Wc[i * HID + col];
#pragma unroll
        for (int r = 0; r < 4; r++) accC[r] += cu[r0 + r][i] * wc;
    }
    for (int i = 0; i < HID; i++) {
        float wc = Wc[(HIN + i) * HID + col];
#pragma unroll
        for (int r = 0; r < 4; r++) accC[r] += rh[r0 + r][i] * wc;
    }

    float hpv[4];
#pragma unroll
    for (int r = 0; r < 4; r++) {
        int n = (row0 + r0 + r) & (NN - 1);
        float c = tanhf(bc[n] + accC[r]);
        hpv[r] = uu[r] * hval[r] + (1.f - uu[r]) * c;
        hp_out[(size_t)(row0 + r0 + r) * HID + col] = hpv[r];
    }
    __syncthreads();
#pragma unroll
    for (int r = 0; r < 4; r++) rh[r0 + r][col] = hpv[r];
    __syncthreads();

    float accT[4];
#pragma unroll
    for (int r = 0; r < 4; r++) accT[r] = 0.f;
    for (int i = 0; i < HID; i++) {
        float w = Rp[i * HID + col];
#pragma unroll
        for (int r = 0; r < 4; r++) accT[r] += rh[r0 + r][i] * w;
    }
#pragma unroll
    for (int r = 0; r < 4; r++)
        g_t[(size_t)(row0 + r0 + r) * HID + col] = accT[r];
}

// ---------------- K5: A[b] = t[b] @ hp[b]^T via packed f32x2 FMA ----------------
// A stored duplicated ({v,v} pairs) so a-operands load as ready-made f32x2.
// B staggered (+4 words per 32 cols) so 16B b-loads are conflict-free.
static constexpr int AW = 264;   // 256 floats (128 values x2) + pad
static constexpr int BW = 140;   // 128 + stagger(12) + pad

__device__ __forceinline__ int bofs(int c) { return c + ((c >> 5) << 2); }

__global__ __launch_bounds__(256, 2) void k5_decode(const float* __restrict__ hp,
                                                    float* __restrict__ A) {
    __shared__ float As2[16][AW];
    __shared__ float Bs [16][BW];

    const int b    = blockIdx.z;
    const int row0 = blockIdx.y * 128;
    const int col0 = blockIdx.x * 128;
    const float* tm = g_t + (size_t)b * NN * HID;
    const float* hb = hp  + (size_t)b * NN * HID;

    const int tid = threadIdx.x;
    const int tx = tid & 15, ty = tid >> 4;

    unsigned long long acc[8][4];
#pragma unroll
    for (int u = 0; u < 8; u++)
#pragma unroll
        for (int v = 0; v < 4; v++) acc[u][v] = 0ull;

    const int li = tid >> 2;          // 0..63
    const int lk = (tid & 3) * 4;     // 0,4,8,12

    // prologue: K-tile 0 into registers
    float4 va0, va1, vb0, vb1;
    va0 = *reinterpret_cast<const float4*>(&tm[(size_t)(row0 + li)      * HID + lk]);
    va1 = *reinterpret_cast<const float4*>(&tm[(size_t)(row0 + li + 64) * HID + lk]);
    vb0 = *reinterpret_cast<const float4*>(&hb[(size_t)(col0 + li)      * HID + lk]);
    vb1 = *reinterpret_cast<const float4*>(&hb[(size_t)(col0 + li + 64) * HID + lk]);

    for (int k0 = 0; k0 < HID; k0 += 16) {
        // stage regs -> smem (A duplicated, B staggered)
        {
            float av[4] = {va0.x, va0.y, va0.z, va0.w};
            float aw[4] = {va1.x, va1.y, va1.z, va1.w};
            float bv[4] = {vb0.x, vb0.y, vb0.z, vb0.w};
            float bw[4] = {vb1.x, vb1.y, vb1.z, vb1.w};
#pragma unroll
            for (int j = 0; j < 4; j++) {
                *reinterpret_cast<float2*>(&As2[lk + j][2 * li])        = make_float2(av[j], av[j]);
                *reinterpret_cast<float2*>(&As2[lk + j][2 * (li + 64)]) = make_float2(aw[j], aw[j]);
                Bs[lk + j][bofs(li)]      = bv[j];
                Bs[lk + j][bofs(li + 64)] = bw[j];
            }
        }
        __syncthreads();

        // prefetch next K-tile
        if (k0 + 16 < HID) {
            int kn = k0 + 16 + lk;
            va0 = *reinterpret_cast<const float4*>(&tm[(size_t)(row0 + li)      * HID + kn]);
            va1 = *reinterpret_cast<const float4*>(&tm[(size_t)(row0 + li + 64) * HID + kn]);
            vb0 = *reinterpret_cast<const float4*>(&hb[(size_t)(col0 + li)      * HID + kn]);
            vb1 = *reinterpret_cast<const float4*>(&hb[(size_t)(col0 + li + 64) * HID + kn]);
        }

        const int abase = 16 * ty;                       // duplicated pairs for rows ty*8..+7
        const int bbase = 8 * tx + ((tx >> 2) << 2);     // staggered b pairs

#pragma unroll
        for (int kk = 0; kk < 16; kk++) {
            const ulonglong2 aA = *reinterpret_cast<const ulonglong2*>(&As2[kk][abase + 0]);
            const ulonglong2 aB = *reinterpret_cast<const ulonglong2*>(&As2[kk][abase + 4]);
            const ulonglong2 aC = *reinterpret_cast<const ulonglong2*>(&As2[kk][abase + 8]);
            const ulonglong2 aD = *reinterpret_cast<const ulonglong2*>(&As2[kk][abase + 12]);
            const ulonglong2 bA = *reinterpret_cast<const ulonglong2*>(&Bs[kk][bbase + 0]);
            const ulonglong2 bB = *reinterpret_cast<const ulonglong2*>(&Bs[kk][bbase + 4]);
            unsigned long long ap[8] = {aA.x, aA.y, aB.x, aB.y, aC.x, aC.y, aD.x, aD.y};
            unsigned long long bp[4] = {bA.x, bA.y, bB.x, bB.y};
#pragma unroll
            for (int u = 0; u < 8; u++) {
#pragma unroll
                for (int v = 0; v < 4; v++) FMA2(acc[u][v], ap[u], bp[v]);
            }
        }
        __syncthreads();
    }

    float* Ab = A + (size_t)b * NN * NN;
#pragma unroll
    for (int u = 0; u < 8; u++) {
        int rr = row0 + ty * 8 + u;
        float f0, f1, f2, f3, f4, f5, f6, f7;
        UNPACK2(f0, f1, acc[u][0]);
        UNPACK2(f2, f3, acc[u][1]);
        UNPACK2(f4, f5, acc[u][2]);
        UNPACK2(f6, f7, acc[u][3]);
        float4 w0 = make_float4(f0, f1, f2, f3);
        float4 w1 = make_float4(f4, f5, f6, f7);
        *reinterpret_cast<float4*>(&Ab[(size_t)rr * NN + col0 + tx * 8 + 0]) = w0;
        *reinterpret_cast<float4*>(&Ab[(size_t)rr * NN + col0 + tx * 8 + 4]) = w1;
    }
}

// ---------------- launch ----------------
extern "C" void kernel_launch(void* const* d_in, const int* in_sizes, int n_in,
                              void* d_out, int out_size) {
    (void)in_sizes; (void)n_in; (void)out_size;
    const float* x    = (const float*)d_in[0];
    const float* a    = (const float*)d_in[1];
    const float* h    = (const float*)d_in[2];
    const float* kern = (const float*)d_in[3];
    const float* asf  = (const float*)d_in[4];
    const float* anb  = (const float*)d_in[5];
    const float* bias = (const float*)d_in[6];
    const float* bu   = (const float*)d_in[7];
    const float* br   = (const float*)d_in[8];
    const float* bc   = (const float*)d_in[9];
    const float* Wu   = (const float*)d_in[10];
    const float* Wr   = (const float*)d_in[11];
    const float* Wc   = (const float*)d_in[12];
    const float* Rp   = (const float*)d_in[13];

    float* A  = (float*)d_out;                       // [B,N,N]
    float* hp = A + (size_t)BQ * NN * NN;            // [B,N,HID]

    k1_project <<< (BQ * NN) / 8, 128 >>> (x, kern, asf, anb);
    k2_attention <<< BQ * NN, 128 >>> (a, bias);
    k3_gates <<< (BQ * NN) / 16, 512 >>> (h, bu, br, bc, Wu, Wr, Wc, Rp, hp);
    dim3 g5(NN / 128, NN / 128, BQ);
    k5_decode <<< g5, 256 >>> (hp, A);
}

// round 6
// speedup vs baseline: 1.4396x; 1.4396x over previous
#include <cuda_runtime.h>
#include <cuda_bf16.h>
#include <cstdint>

// Problem constants
static constexpr int BQ  = 2;
static constexpr int NN  = 2048;
static constexpr int FF  = 64;
static constexpr int HH  = 4;
static constexpr int HID = 128;
static constexpr int HIN = 128;   // H*C

// Arch-specific gate: tcgen05 is only legal in the sm_103a target; the harness
// also compiles a plain compute_103 pass which must get a fallback body.
#if defined(__CUDA_ARCH_FEAT_SM103_ALL) || \
    (defined(__CUDA_ARCH_SPECIFIC__) && (__CUDA_ARCH_SPECIFIC__ == 1030))
#define HAS_TCGEN05 1
#else
#define HAS_TCGEN05 0
#endif

// ---------------- device scratch ----------------
__device__ float g_xp[BQ * NN * HIN];
__device__ float g_es[BQ * NN * HH];
__device__ float g_en[BQ * NN * HH];
__device__ float g_cu[BQ * NN * HIN];
// bf16 hi/lo splits of t = hp@Rp and hp
__device__ __nv_bfloat16 g_th[BQ * NN * HID];
__device__ __nv_bfloat16 g_tl[BQ * NN * HID];
__device__ __nv_bfloat16 g_ph[BQ * NN * HID];
__device__ __nv_bfloat16 g_pl[BQ * NN * HID];

// ---------------- K1: xp = x @ kernel, es/en reductions ----------------
__global__ void k1_project(const float* __restrict__ x,
                           const float* __restrict__ kern,
                           const float* __restrict__ attn_self,
                           const float* __restrict__ attn_nei) {
    __shared__ float xs[8][FF];
    const int row0 = blockIdx.x * 8;
    const int t = threadIdx.x;

    for (int i = t; i < 8 * FF; i += 128) {
        int r = i / FF, f = i % FF;
        xs[r][f] = x[(size_t)(row0 + r) * FF + f];
    }
    __syncthreads();

    const float a_s = attn_self[t];
    const float a_n = attn_nei[t];
    const int h = t >> 5, lane = t & 31;

    float acc[8];
#pragma unroll
    for (int r = 0; r < 8; r++) acc[r] = 0.f;

    for (int f = 0; f < FF; f++) {
        float w = kern[f * HIN + t];
#pragma unroll
        for (int r = 0; r < 8; r++) acc[r] += xs[r][f] * w;
    }

#pragma unroll
    for (int r = 0; r < 8; r++) {
        g_xp[(size_t)(row0 + r) * HIN + t] = acc[r];
        float ps = acc[r] * a_s;
        float pn = acc[r] * a_n;
#pragma unroll
        for (int o = 16; o > 0; o >>= 1) {
            ps += __shfl_down_sync(0xffffffffu, ps, o);
            pn += __shfl_down_sync(0xffffffffu, pn, o);
        }
        if (lane == 0) {
            g_es[(row0 + r) * HH + h] = ps;
            g_en[(row0 + r) * HH + h] = pn;
        }
    }
}

// ---------------- K2: masked softmax attention + sparse aggregation ----------------
static constexpr int MAXNBR = 512;

__global__ void k2_attention(const float* __restrict__ a,
                             const float* __restrict__ bias_gat) {
    __shared__ int   nbr[MAXNBR];
    __shared__ float wgt[HH][MAXNBR];
    __shared__ int   cnt;

    const int bi = blockIdx.x;
    const int b = bi >> 11;
    const int t = threadIdx.x;
    const int h = t >> 5, lane = t & 31;
    const int base = b * NN;

    if (t == 0) cnt = 0;
    __syncthreads();

    const float4* arow4 = reinterpret_cast<const float4*>(a + (size_t)bi * NN);
    for (int j4 = t; j4 < NN / 4; j4 += 128) {
        float4 v = arow4[j4];
        if (v.x != 0.f) { int p = atomicAdd(&cnt, 1); if (p < MAXNBR) nbr[p] = j4 * 4 + 0; }
        if (v.y != 0.f) { int p = atomicAdd(&cnt, 1); if (p < MAXNBR) nbr[p] = j4 * 4 + 1; }
        if (v.z != 0.f) { int p = atomicAdd(&cnt, 1); if (p < MAXNBR) nbr[p] = j4 * 4 + 2; }
        if (v.w != 0.f) { int p = atomicAdd(&cnt, 1); if (p < MAXNBR) nbr[p] = j4 * 4 + 3; }
    }
    __syncthreads();
    const int K = cnt < MAXNBR ? cnt : MAXNBR;

    const float esi = g_es[bi * HH + h];

    float m = -1e30f;
    for (int k = lane; k < K; k += 32) {
        float v = esi + g_en[(base + nbr[k]) * HH + h];
        float e = v > 0.f ? v : 0.2f * v;
        wgt[h][k] = e;
        m = fmaxf(m, e);
    }
#pragma unroll
    for (int o = 16; o > 0; o >>= 1) m = fmaxf(m, __shfl_xor_sync(0xffffffffu, m, o));
    __syncwarp();

    float s = 0.f;
    for (int k = lane; k < K; k += 32) {
        float w = expf(wgt[h][k] - m);
        wgt[h][k] = w;
        s += w;
    }
#pragma unroll
    for (int o = 16; o > 0; o >>= 1) s += __shfl_xor_sync(0xffffffffu, s, o);
    const float inv = 1.f / s;
    __syncwarp();

    float acc = 0.f;
    for (int k = 0; k < K; k++) {
        acc += wgt[h][k] * g_xp[(size_t)(base + nbr[k]) * HIN + t];
    }
    g_cu[(size_t)bi * HIN + t] = acc * inv + bias_gat[t];
}

// ---------------- K3: fused GRU gates + h'@R_p + bf16 hi/lo split ----------------
__global__ __launch_bounds__(512) void k3_gates(
        const float* __restrict__ h_in,
        const float* __restrict__ bu, const float* __restrict__ br,
        const float* __restrict__ bc,
        const float* __restrict__ Wu, const float* __restrict__ Wr,
        const float* __restrict__ Wc, const float* __restrict__ Rp,
        float* __restrict__ hp_out) {
    __shared__ float cu[16][HIN];
    __shared__ float hh[16][HID];
    __shared__ float rh[16][HID];

    const int row0 = blockIdx.x * 16;
    const int t = threadIdx.x;
    const int col = t & 127;
    const int r0 = (t >> 7) * 4;

    float hval[4];
#pragma unroll
    for (int r = 0; r < 4; r++) {
        cu[r0 + r][col] = g_cu[(size_t)(row0 + r0 + r) * HIN + col];
        hval[r] = h_in[(size_t)(row0 + r0 + r) * HID + col];
        hh[r0 + r][col] = hval[r];
    }
    __syncthreads();

    float accU[4], accR[4];
#pragma unroll
    for (int r = 0; r < 4; r++) { accU[r] = 0.f; accR[r] = 0.f; }

    for (int i = 0; i < HIN; i++) {
        float wu = Wu[i * HID + col];
        float wr = Wr[i * HID + col];
#pragma unroll
        for (int r = 0; r < 4; r++) {
            float z = cu[r0 + r][i];
            accU[r] += z * wu;
            accR[r] += z * wr;
        }
    }
    for (int i = 0; i < HID; i++) {
        float wu = Wu[(HIN + i) * HID + col];
        float wr = Wr[(HIN + i) * HID + col];
#pragma unroll
        for (int r = 0; r < 4; r++) {
            float z = hh[r0 + r][i];
            accU[r] += z * wu;
            accR[r] += z * wr;
        }
    }

    float uu[4];
#pragma unroll
    for (int r = 0; r < 4; r++) {
        int n = (row0 + r0 + r) & (NN - 1);
        float u  = 1.f / (1.f + expf(-(bu[n] + accU[r])));
        float rr = 1.f / (1.f + expf(-(br[n] + accR[r])));
        uu[r] = u;
        rh[r0 + r][col] = rr * hval[r];
    }
    __syncthreads();

    float accC[4];
#pragma unroll
    for (int r = 0; r < 4; r++) accC[r] = 0.f;

    for (int i = 0; i < HIN; i++) {
        float wc = Wc[i * HID + col];
#pragma unroll
        for (int r = 0; r < 4; r++) accC[r] += cu[r0 + r][i] * wc;
    }
    for (int i = 0; i < HID; i++) {
        float wc = Wc[(HIN + i) * HID + col];
#pragma unroll
        for (int r = 0; r < 4; r++) accC[r] += rh[r0 + r][i] * wc;
    }

    float hpv[4];
#pragma unroll
    for (int r = 0; r < 4; r++) {
        int n = (row0 + r0 + r) & (NN - 1);
        float c = tanhf(bc[n] + accC[r]);
        hpv[r] = uu[r] * hval[r] + (1.f - uu[r]) * c;
        size_t idx = (size_t)(row0 + r0 + r) * HID + col;
        hp_out[idx] = hpv[r];
        __nv_bfloat16 ph = __float2bfloat16(hpv[r]);
        g_ph[idx] = ph;
        g_pl[idx] = __float2bfloat16(hpv[r] - __bfloat162float(ph));
    }
    __syncthreads();
#pragma unroll
    for (int r = 0; r < 4; r++) rh[r0 + r][col] = hpv[r];
    __syncthreads();

    float accT[4];
#pragma unroll
    for (int r = 0; r < 4; r++) accT[r] = 0.f;
    for (int i = 0; i < HID; i++) {
        float w = Rp[i * HID + col];
#pragma unroll
        for (int r = 0; r < 4; r++) accT[r] += rh[r0 + r][i] * w;
    }
#pragma unroll
    for (int r = 0; r < 4; r++) {
        size_t idx = (size_t)(row0 + r0 + r) * HID + col;
        __nv_bfloat16 th = __float2bfloat16(accT[r]);
        g_th[idx] = th;
        g_tl[idx] = __float2bfloat16(accT[r] - __bfloat162float(th));
    }
}

// ---------------- K5: A = t @ hp^T via tcgen05 bf16-split (3-term) ----------------
static constexpr int SM_AHI = 1024;
static constexpr int SM_ALO = 1024 + 32768;
static constexpr int SM_BHI = 1024 + 65536;
static constexpr int SM_BLO = 1024 + 98304;
static constexpr int SM_TOTAL_K5 = 1024 + 131072;

#if HAS_TCGEN05
// ---------------- tcgen05 / mbarrier helpers (sm_103a target only) ----------------
__device__ __forceinline__ uint32_t elect_one_pred() {
    uint32_t p;
    asm volatile("{.reg .pred p; elect.sync _|p, 0xFFFFFFFF; selp.b32 %0, 1, 0, p;}" : "=r"(p));
    return p;
}
__device__ __forceinline__ uint32_t smem_u32(const void* p) {
    uint32_t a;
    asm("{.reg .u64 t; cvta.to.shared.u64 t, %1; cvt.u32.u64 %0, t;}" : "=r"(a) : "l"(p));
    return a;
}
#define MBAR_INIT(addr, cnt) \
    asm volatile("mbarrier.init.shared.b64 [%0], %1;" :: "r"(addr), "r"(cnt) : "memory")
#define MBAR_INVAL(addr) \
    asm volatile("mbarrier.inval.shared.b64 [%0];" :: "r"(addr) : "memory")
__device__ __forceinline__ void mbar_wait(uint32_t addr, uint32_t parity) {
    asm volatile(
        "{.reg .pred P;\n\t"
        "WL_%=: mbarrier.try_wait.parity.acquire.cta.shared::cta.b64 P, [%0], %1, 0x989680;\n\t"
        "@P bra WD_%=; bra WL_%=; WD_%=:}\n\t"
        :: "r"(addr), "r"(parity) : "memory");
}
#define TC_ALLOC(sm_addr, n) \
    asm volatile("tcgen05.alloc.cta_group::1.sync.aligned.shared::cta.b32 [%0], %1;" \
                 :: "r"(sm_addr), "r"(n) : "memory")
#define TC_DEALLOC(tmem, n) \
    asm volatile("tcgen05.dealloc.cta_group::1.sync.aligned.b32 %0, %1;" :: "r"(tmem), "r"(n))
#define TC_RELINQ() \
    asm volatile("tcgen05.relinquish_alloc_permit.cta_group::1.sync.aligned;")
#define TC_COMMIT(mbar) \
    asm volatile("tcgen05.commit.cta_group::1.mbarrier::arrive::one.shared::cluster.b64 [%0];" \
                 :: "r"(mbar) : "memory")
#define TC_FENCE_AFTER() asm volatile("tcgen05.fence::after_thread_sync;" ::: "memory")
#define FENCE_ASYNC_SHARED() asm volatile("fence.proxy.async.shared::cta;" ::: "memory")
#define TC_WAIT_LD() asm volatile("tcgen05.wait::ld.sync.aligned;" ::: "memory")

__device__ __forceinline__ void tc_mma_f16_ss(uint32_t d, uint64_t adesc, uint64_t bdesc,
                                              uint32_t idesc, uint32_t en) {
    asm volatile(
        "{.reg .pred p; setp.ne.u32 p, %5, 0;\n\t"
        "tcgen05.mma.cta_group::1.kind::f16 [%0], %1, %2, %3, {%4, %4, %4, %4}, p;}\n\t"
        :: "r"(d), "l"(adesc), "l"(bdesc), "r"(idesc), "r"(0u), "r"(en) : "memory");
}

#define TC_LD_X32(r, addr) \
    asm volatile( \
        "tcgen05.ld.sync.aligned.32x32b.x32.b32 " \
        "{%0,%1,%2,%3,%4,%5,%6,%7,%8,%9,%10,%11,%12,%13,%14,%15," \
        "%16,%17,%18,%19,%20,%21,%22,%23,%24,%25,%26,%27,%28,%29,%30,%31}, [%32];" \
        : "=r"((r)[0]),"=r"((r)[1]),"=r"((r)[2]),"=r"((r)[3]), \
          "=r"((r)[4]),"=r"((r)[5]),"=r"((r)[6]),"=r"((r)[7]), \
          "=r"((r)[8]),"=r"((r)[9]),"=r"((r)[10]),"=r"((r)[11]), \
          "=r"((r)[12]),"=r"((r)[13]),"=r"((r)[14]),"=r"((r)[15]), \
          "=r"((r)[16]),"=r"((r)[17]),"=r"((r)[18]),"=r"((r)[19]), \
          "=r"((r)[20]),"=r"((r)[21]),"=r"((r)[22]),"=r"((r)[23]), \
          "=r"((r)[24]),"=r"((r)[25]),"=r"((r)[26]),"=r"((r)[27]), \
          "=r"((r)[28]),"=r"((r)[29]),"=r"((r)[30]),"=r"((r)[31]) \
        : "r"(addr))

// SW128 smem descriptor: layout=2, version=1, SBO=64 (1024B per 8-row group), LBO=1
static constexpr uint64_t DESC_BASE_SW128 =
    (uint64_t(2) << 61) | (uint64_t(1) << 46) | (uint64_t(64) << 32) | (uint64_t(1) << 16);
__device__ __forceinline__ uint64_t make_desc(uint32_t addr) {
    return DESC_BASE_SW128 | ((uint64_t)(addr >> 4) & 0x3FFF);
}

static constexpr uint32_t IDESC_F16 = 0x8200490u;  // F32 acc, bf16 x bf16, M=128, N=128

// descriptor start-address offset (16B units) for K-step k of a 128x128 bf16
// blocked-SW128 tile: within atom-col (+2 per 16 bf16), atom-col 1 at +1024
__device__ __forceinline__ uint64_t kofs(int k) {
    return (uint64_t)((k & 3) * 2 + (k >> 2) * 1024);
}

__device__ __forceinline__ void copy_tile(const __nv_bfloat16* __restrict__ src,
                                          char* __restrict__ dst, int tid) {
    const uint4* s4 = reinterpret_cast<const uint4*>(src);
#pragma unroll
    for (int q = tid; q < 2048; q += 256) {
        uint4 v = s4[q];
        int r = q >> 4, c16 = q & 15;
        int boff = ((r >> 3) + ((c16 >> 3) << 4)) * 1024 + (r & 7) * 128 + (c16 & 7) * 16;
        boff ^= ((boff >> 3) & 0x70);
        *reinterpret_cast<uint4*>(dst + boff) = v;
    }
}
#endif  // HAS_TCGEN05

__global__ __launch_bounds__(256, 1)
void k5_tc(const float* __restrict__ hp_unused, float* __restrict__ A) {
#if HAS_TCGEN05
    extern __shared__ char smem[];
    const uint32_t sbase = smem_u32(smem);
    const int tid = threadIdx.x;
    const int wid = tid >> 5, lane = tid & 31;

    const int b    = blockIdx.z;
    const int row0 = blockIdx.y * 128;
    const int col0 = blockIdx.x * 128;
    const size_t bofs = (size_t)b * NN * HID;

    if (wid == 0) TC_ALLOC(sbase, 128);
    if (tid == 0) MBAR_INIT(sbase + 8, 1);

    copy_tile(g_th + bofs + (size_t)row0 * HID, smem + SM_AHI, tid);
    copy_tile(g_tl + bofs + (size_t)row0 * HID, smem + SM_ALO, tid);
    copy_tile(g_ph + bofs + (size_t)col0 * HID, smem + SM_BHI, tid);
    copy_tile(g_pl + bofs + (size_t)col0 * HID, smem + SM_BLO, tid);
    FENCE_ASYNC_SHARED();
    __syncthreads();

    uint32_t tmem;
    asm volatile("ld.shared.b32 %0, [%1];" : "=r"(tmem) : "r"(sbase));

    if (wid == 0) {
        TC_RELINQ();
        if (elect_one_pred()) {
            const uint64_t dAh = make_desc(sbase + SM_AHI);
            const uint64_t dAl = make_desc(sbase + SM_ALO);
            const uint64_t dBh = make_desc(sbase + SM_BHI);
            const uint64_t dBl = make_desc(sbase + SM_BLO);
#pragma unroll
            for (int k = 0; k < 8; k++)
                tc_mma_f16_ss(tmem, dAh + kofs(k), dBh + kofs(k), IDESC_F16, k > 0);
#pragma unroll
            for (int k = 0; k < 8; k++)
                tc_mma_f16_ss(tmem, dAh + kofs(k), dBl + kofs(k), IDESC_F16, 1);
#pragma unroll
            for (int k = 0; k < 8; k++)
                tc_mma_f16_ss(tmem, dAl + kofs(k), dBh + kofs(k), IDESC_F16, 1);
            TC_COMMIT(sbase + 8);
        }
    }

    mbar_wait(sbase + 8, 0);
    TC_FENCE_AFTER();

    // epilogue: 8 warps; warp = (sub, half). sub = TMEM subpartition (rows),
    // half = N-column half. Each warp: 2x LDTM X32 -> 64 fp32 -> STG.
    {
        const int sub = wid & 3, half = wid >> 2;
        const int colb = half * 64;
        uint32_t d0[32], d1[32];
        TC_LD_X32(d0, tmem + colb);
        TC_LD_X32(d1, tmem + colb + 32);
        TC_WAIT_LD();

        float* out = A + (size_t)b * NN * NN + (size_t)(row0 + sub * 32 + lane) * NN
                     + col0 + colb;
#pragma unroll
        for (int c = 0; c < 32; c += 4) {
            float4 w = make_float4(__uint_as_float(d0[c]), __uint_as_float(d0[c + 1]),
                                   __uint_as_float(d0[c + 2]), __uint_as_float(d0[c + 3]));
            *reinterpret_cast<float4*>(out + c) = w;
        }
#pragma unroll
        for (int c = 0; c < 32; c += 4) {
            float4 w = make_float4(__uint_as_float(d1[c]), __uint_as_float(d1[c + 1]),
                                   __uint_as_float(d1[c + 2]), __uint_as_float(d1[c + 3]));
            *reinterpret_cast<float4*>(out + 32 + c) = w;
        }
    }

    __syncthreads();
    if (tid == 0) MBAR_INVAL(sbase + 8);
    __syncthreads();
    if (wid == 0) TC_DEALLOC(tmem, 128);
#else
    // SIMT fallback for the compute_103 (non-'a') compile pass. Never runs on
    // sm_103a hardware (exact-match cubin is selected), but must be correct.
    const int tid = threadIdx.x;
    const int b    = blockIdx.z;
    const int row0 = blockIdx.y * 128;
    const int col0 = blockIdx.x * 128;
    const size_t bofs = (size_t)b * NN * HID;
    for (int e = tid; e < 128 * 128; e += 256) {
        int r = e >> 7, c = e & 127;
        const __nv_bfloat16* th = g_th + bofs + (size_t)(row0 + r) * HID;
        const __nv_bfloat16* tl = g_tl + bofs + (size_t)(row0 + r) * HID;
        const __nv_bfloat16* ph = g_ph + bofs + (size_t)(col0 + c) * HID;
        const __nv_bfloat16* pl = g_pl + bofs + (size_t)(col0 + c) * HID;
        float acc = 0.f;
        for (int k = 0; k < HID; k++) {
            float av = __bfloat162float(th[k]) + __bfloat162float(tl[k]);
            float bv = __bfloat162float(ph[k]) + __bfloat162float(pl[k]);
            acc += av * bv;
        }
        A[(size_t)b * NN * NN + (size_t)(row0 + r) * NN + col0 + c] = acc;
    }
    (void)hp_unused;
#endif
}

// ---------------- launch ----------------
extern "C" void kernel_launch(void* const* d_in, const int* in_sizes, int n_in,
                              void* d_out, int out_size) {
    (void)in_sizes; (void)n_in; (void)out_size;
    const float* x    = (const float*)d_in[0];
    const float* a    = (const float*)d_in[1];
    const float* h    = (const float*)d_in[2];
    const float* kern = (const float*)d_in[3];
    const float* asf  = (const float*)d_in[4];
    const float* anb  = (const float*)d_in[5];
    const float* bias = (const float*)d_in[6];
    const float* bu   = (const float*)d_in[7];
    const float* br   = (const float*)d_in[8];
    const float* bc   = (const float*)d_in[9];
    const float* Wu   = (const float*)d_in[10];
    const float* Wr   = (const float*)d_in[11];
    const float* Wc   = (const float*)d_in[12];
    const float* Rp   = (const float*)d_in[13];

    float* A  = (float*)d_out;                       // [B,N,N]
    float* hp = A + (size_t)BQ * NN * NN;            // [B,N,HID]

    static bool attr_set = false;
    if (!attr_set) {
        cudaFuncSetAttribute(k5_tc, cudaFuncAttributeMaxDynamicSharedMemorySize, SM_TOTAL_K5);
        attr_set = true;
    }

    k1_project <<< (BQ * NN) / 8, 128 >>> (x, kern, asf, anb);
    k2_attention <<< BQ * NN, 128 >>> (a, bias);
    k3_gates <<< (BQ * NN) / 16, 512 >>> (h, bu, br, bc, Wu, Wr, Wc, Rp, hp);
    dim3 g5(NN / 128, NN / 128, BQ);
    k5_tc <<< g5, 256, SM_TOTAL_K5 >>> (hp, A);
}

// round 8
// speedup vs baseline: 1.6497x; 1.1459x over previous
#include <cuda_runtime.h>
#include <cuda_bf16.h>
#include <cstdint>

// Problem constants
static constexpr int BQ  = 2;
static constexpr int NN  = 2048;
static constexpr int FF  = 64;
static constexpr int HH  = 4;
static constexpr int HID = 128;
static constexpr int HIN = 128;   // H*C

// Arch-specific gate: tcgen05 is only legal in the sm_103a target; the harness
// also compiles a plain compute_103 pass which must get a fallback body.
#if defined(__CUDA_ARCH_FEAT_SM103_ALL) || \
    (defined(__CUDA_ARCH_SPECIFIC__) && (__CUDA_ARCH_SPECIFIC__ == 1030))
#define HAS_TCGEN05 1
#else
#define HAS_TCGEN05 0
#endif

// ---------------- device scratch ----------------
__device__ float g_xp[BQ * NN * HIN];
__device__ float g_es[BQ * NN * HH];
__device__ float g_en[BQ * NN * HH];
__device__ float g_cu[BQ * NN * HIN];
// bf16 hi/lo splits of t = hp@Rp and hp
__device__ __nv_bfloat16 g_th[BQ * NN * HID];
__device__ __nv_bfloat16 g_tl[BQ * NN * HID];
__device__ __nv_bfloat16 g_ph[BQ * NN * HID];
__device__ __nv_bfloat16 g_pl[BQ * NN * HID];

// ---------------- K1: xp = x @ kernel, es/en reductions ----------------
__global__ void k1_project(const float* __restrict__ x,
                           const float* __restrict__ kern,
                           const float* __restrict__ attn_self,
                           const float* __restrict__ attn_nei) {
    __shared__ float xs[8][FF];
    const int row0 = blockIdx.x * 8;
    const int t = threadIdx.x;

    for (int i = t; i < 8 * FF; i += 128) {
        int r = i / FF, f = i % FF;
        xs[r][f] = x[(size_t)(row0 + r) * FF + f];
    }
    __syncthreads();

    const float a_s = attn_self[t];
    const float a_n = attn_nei[t];
    const int h = t >> 5, lane = t & 31;

    float acc[8];
#pragma unroll
    for (int r = 0; r < 8; r++) acc[r] = 0.f;

    for (int f = 0; f < FF; f++) {
        float w = kern[f * HIN + t];
#pragma unroll
        for (int r = 0; r < 8; r++) acc[r] += xs[r][f] * w;
    }

#pragma unroll
    for (int r = 0; r < 8; r++) {
        g_xp[(size_t)(row0 + r) * HIN + t] = acc[r];
        float ps = acc[r] * a_s;
        float pn = acc[r] * a_n;
#pragma unroll
        for (int o = 16; o > 0; o >>= 1) {
            ps += __shfl_down_sync(0xffffffffu, ps, o);
            pn += __shfl_down_sync(0xffffffffu, pn, o);
        }
        if (lane == 0) {
            g_es[(row0 + r) * HH + h] = ps;
            g_en[(row0 + r) * HH + h] = pn;
        }
    }
}

// ---------------- K2: masked softmax attention + sparse aggregation ----------------
static constexpr int MAXNBR = 512;

__global__ void k2_attention(const float* __restrict__ a,
                             const float* __restrict__ bias_gat) {
    __shared__ int   nbr[MAXNBR];
    __shared__ float wgt[HH][MAXNBR];
    __shared__ int   cnt;

    const int bi = blockIdx.x;
    const int b = bi >> 11;
    const int t = threadIdx.x;
    const int h = t >> 5, lane = t & 31;
    const int base = b * NN;

    if (t == 0) cnt = 0;
    __syncthreads();

    const float4* arow4 = reinterpret_cast<const float4*>(a + (size_t)bi * NN);
    for (int j4 = t; j4 < NN / 4; j4 += 128) {
        float4 v = arow4[j4];
        if (v.x != 0.f) { int p = atomicAdd(&cnt, 1); if (p < MAXNBR) nbr[p] = j4 * 4 + 0; }
        if (v.y != 0.f) { int p = atomicAdd(&cnt, 1); if (p < MAXNBR) nbr[p] = j4 * 4 + 1; }
        if (v.z != 0.f) { int p = atomicAdd(&cnt, 1); if (p < MAXNBR) nbr[p] = j4 * 4 + 2; }
        if (v.w != 0.f) { int p = atomicAdd(&cnt, 1); if (p < MAXNBR) nbr[p] = j4 * 4 + 3; }
    }
    __syncthreads();
    const int K = cnt < MAXNBR ? cnt : MAXNBR;

    const float esi = g_es[bi * HH + h];

    float m = -1e30f;
    for (int k = lane; k < K; k += 32) {
        float v = esi + g_en[(base + nbr[k]) * HH + h];
        float e = v > 0.f ? v : 0.2f * v;
        wgt[h][k] = e;
        m = fmaxf(m, e);
    }
#pragma unroll
    for (int o = 16; o > 0; o >>= 1) m = fmaxf(m, __shfl_xor_sync(0xffffffffu, m, o));
    __syncwarp();

    float s = 0.f;
    for (int k = lane; k < K; k += 32) {
        float w = expf(wgt[h][k] - m);
        wgt[h][k] = w;
        s += w;
    }
#pragma unroll
    for (int o = 16; o > 0; o >>= 1) s += __shfl_xor_sync(0xffffffffu, s, o);
    const float inv = 1.f / s;
    __syncwarp();

    float acc = 0.f;
    for (int k = 0; k < K; k++) {
        acc += wgt[h][k] * g_xp[(size_t)(base + nbr[k]) * HIN + t];
    }
    g_cu[(size_t)bi * HIN + t] = acc * inv + bias_gat[t];
}

// ---------------- K3: fused GRU gates + h'@R_p + bf16 hi/lo split ----------------
__global__ __launch_bounds__(512) void k3_gates(
        const float* __restrict__ h_in,
        const float* __restrict__ bu, const float* __restrict__ br,
        const float* __restrict__ bc,
        const float* __restrict__ Wu, const float* __restrict__ Wr,
        const float* __restrict__ Wc, const float* __restrict__ Rp,
        float* __restrict__ hp_out) {
    __shared__ float cu[16][HIN];
    __shared__ float hh[16][HID];
    __shared__ float rh[16][HID];

    const int row0 = blockIdx.x * 16;
    const int t = threadIdx.x;
    const int col = t & 127;
    const int r0 = (t >> 7) * 4;

    float hval[4];
#pragma unroll
    for (int r = 0; r < 4; r++) {
        cu[r0 + r][col] = g_cu[(size_t)(row0 + r0 + r) * HIN + col];
        hval[r] = h_in[(size_t)(row0 + r0 + r) * HID + col];
        hh[r0 + r][col] = hval[r];
    }
    __syncthreads();

    float accU[4], accR[4];
#pragma unroll
    for (int r = 0; r < 4; r++) { accU[r] = 0.f; accR[r] = 0.f; }

    // pass 1: U and R accumulation (vectorized LDS over i)
    for (int i = 0; i < HIN; i += 4) {
        float wu0 = Wu[(i + 0) * HID + col], wr0 = Wr[(i + 0) * HID + col];
        float wu1 = Wu[(i + 1) * HID + col], wr1 = Wr[(i + 1) * HID + col];
        float wu2 = Wu[(i + 2) * HID + col], wr2 = Wr[(i + 2) * HID + col];
        float wu3 = Wu[(i + 3) * HID + col], wr3 = Wr[(i + 3) * HID + col];
#pragma unroll
        for (int r = 0; r < 4; r++) {
            float4 z = *reinterpret_cast<const float4*>(&cu[r0 + r][i]);
            accU[r] += z.x * wu0 + z.y * wu1 + z.z * wu2 + z.w * wu3;
            accR[r] += z.x * wr0 + z.y * wr1 + z.z * wr2 + z.w * wr3;
        }
    }
    for (int i = 0; i < HID; i += 4) {
        float wu0 = Wu[(HIN + i + 0) * HID + col], wr0 = Wr[(HIN + i + 0) * HID + col];
        float wu1 = Wu[(HIN + i + 1) * HID + col], wr1 = Wr[(HIN + i + 1) * HID + col];
        float wu2 = Wu[(HIN + i + 2) * HID + col], wr2 = Wr[(HIN + i + 2) * HID + col];
        float wu3 = Wu[(HIN + i + 3) * HID + col], wr3 = Wr[(HIN + i + 3) * HID + col];
#pragma unroll
        for (int r = 0; r < 4; r++) {
            float4 z = *reinterpret_cast<const float4*>(&hh[r0 + r][i]);
            accU[r] += z.x * wu0 + z.y * wu1 + z.z * wu2 + z.w * wu3;
            accR[r] += z.x * wr0 + z.y * wr1 + z.z * wr2 + z.w * wr3;
        }
    }

    float uu[4];
#pragma unroll
    for (int r = 0; r < 4; r++) {
        int n = (row0 + r0 + r) & (NN - 1);
        float u  = 1.f / (1.f + expf(-(bu[n] + accU[r])));
        float rr = 1.f / (1.f + expf(-(br[n] + accR[r])));
        uu[r] = u;
        rh[r0 + r][col] = rr * hval[r];
    }
    __syncthreads();

    float accC[4];
#pragma unroll
    for (int r = 0; r < 4; r++) accC[r] = 0.f;

    for (int i = 0; i < HIN; i += 4) {
        float wc0 = Wc[(i + 0) * HID + col];
        float wc1 = Wc[(i + 1) * HID + col];
        float wc2 = Wc[(i + 2) * HID + col];
        float wc3 = Wc[(i + 3) * HID + col];
#pragma unroll
        for (int r = 0; r < 4; r++) {
            float4 z = *reinterpret_cast<const float4*>(&cu[r0 + r][i]);
            accC[r] += z.x * wc0 + z.y * wc1 + z.z * wc2 + z.w * wc3;
        }
    }
    for (int i = 0; i < HID; i += 4) {
        float wc0 = Wc[(HIN + i + 0) * HID + col];
        float wc1 = Wc[(HIN + i + 1) * HID + col];
        float wc2 = Wc[(HIN + i + 2) * HID + col];
        float wc3 = Wc[(HIN + i + 3) * HID + col];
#pragma unroll
        for (int r = 0; r < 4; r++) {
            float4 z = *reinterpret_cast<const float4*>(&rh[r0 + r][i]);
            accC[r] += z.x * wc0 + z.y * wc1 + z.z * wc2 + z.w * wc3;
        }
    }

    float hpv[4];
#pragma unroll
    for (int r = 0; r < 4; r++) {
        int n = (row0 + r0 + r) & (NN - 1);
        float c = tanhf(bc[n] + accC[r]);
        hpv[r] = uu[r] * hval[r] + (1.f - uu[r]) * c;
        size_t idx = (size_t)(row0 + r0 + r) * HID + col;
        hp_out[idx] = hpv[r];
        __nv_bfloat16 ph = __float2bfloat16(hpv[r]);
        g_ph[idx] = ph;
        g_pl[idx] = __float2bfloat16(hpv[r] - __bfloat162float(ph));
    }
    __syncthreads();
#pragma unroll
    for (int r = 0; r < 4; r++) rh[r0 + r][col] = hpv[r];
    __syncthreads();

    float accT[4];
#pragma unroll
    for (int r = 0; r < 4; r++) accT[r] = 0.f;
    for (int i = 0; i < HID; i += 4) {
        float w0 = Rp[(i + 0) * HID + col];
        float w1 = Rp[(i + 1) * HID + col];
        float w2 = Rp[(i + 2) * HID + col];
        float w3 = Rp[(i + 3) * HID + col];
#pragma unroll
        for (int r = 0; r < 4; r++) {
            float4 z = *reinterpret_cast<const float4*>(&rh[r0 + r][i]);
            accT[r] += z.x * w0 + z.y * w1 + z.z * w2 + z.w * w3;
        }
    }
#pragma unroll
    for (int r = 0; r < 4; r++) {
        size_t idx = (size_t)(row0 + r0 + r) * HID + col;
        __nv_bfloat16 th = __float2bfloat16(accT[r]);
        g_th[idx] = th;
        g_tl[idx] = __float2bfloat16(accT[r] - __bfloat162float(th));
    }
}

// ---------------- K5: A = t @ hp^T, tcgen05 bf16-split, persistent col-tiles ----------------
// SMEM byte offsets: [0] tmem ptr, [8] mbar, A hi/lo, then double-buffered B hi/lo.
static constexpr int SM_AHI = 1024;
static constexpr int SM_ALO = 1024 + 32768;
static constexpr int SM_B0H = 1024 + 65536;            // buf0 hi
static constexpr int SM_B0L = 1024 + 65536 + 32768;    // buf0 lo
static constexpr int SM_B1H = 1024 + 131072;           // buf1 hi
static constexpr int SM_B1L = 1024 + 131072 + 32768;   // buf1 lo
static constexpr int SM_TOTAL_K5 = 1024 + 196608;      // ~193 KB
static constexpr int COLT = 4;                          // col tiles per CTA

#if HAS_TCGEN05
// ---------------- tcgen05 / mbarrier helpers (sm_103a target only) ----------------
__device__ __forceinline__ uint32_t elect_one_pred() {
    uint32_t p;
    asm volatile("{.reg .pred p; elect.sync _|p, 0xFFFFFFFF; selp.b32 %0, 1, 0, p;}" : "=r"(p));
    return p;
}
__device__ __forceinline__ uint32_t smem_u32(const void* p) {
    uint32_t a;
    asm("{.reg .u64 t; cvta.to.shared.u64 t, %1; cvt.u32.u64 %0, t;}" : "=r"(a) : "l"(p));
    return a;
}
#define MBAR_INIT(addr, cnt) \
    asm volatile("mbarrier.init.shared.b64 [%0], %1;" :: "r"(addr), "r"(cnt) : "memory")
#define MBAR_INVAL(addr) \
    asm volatile("mbarrier.inval.shared.b64 [%0];" :: "r"(addr) : "memory")
__device__ __forceinline__ void mbar_wait(uint32_t addr, uint32_t parity) {
    asm volatile(
        "{.reg .pred P;\n\t"
        "WL_%=: mbarrier.try_wait.parity.acquire.cta.shared::cta.b64 P, [%0], %1, 0x989680;\n\t"
        "@P bra WD_%=; bra WL_%=; WD_%=:}\n\t"
        :: "r"(addr), "r"(parity) : "memory");
}
#define TC_ALLOC(sm_addr, n) \
    asm volatile("tcgen05.alloc.cta_group::1.sync.aligned.shared::cta.b32 [%0], %1;" \
                 :: "r"(sm_addr), "r"(n) : "memory")
#define TC_DEALLOC(tmem, n) \
    asm volatile("tcgen05.dealloc.cta_group::1.sync.aligned.b32 %0, %1;" :: "r"(tmem), "r"(n))
#define TC_RELINQ() \
    asm volatile("tcgen05.relinquish_alloc_permit.cta_group::1.sync.aligned;")
#define TC_COMMIT(mbar) \
    asm volatile("tcgen05.commit.cta_group::1.mbarrier::arrive::one.shared::cluster.b64 [%0];" \
                 :: "r"(mbar) : "memory")
#define TC_FENCE_AFTER()  asm volatile("tcgen05.fence::after_thread_sync;" ::: "memory")
#define TC_FENCE_BEFORE() asm volatile("tcgen05.fence::before_thread_sync;" ::: "memory")
#define FENCE_ASYNC_SHARED() asm volatile("fence.proxy.async.shared::cta;" ::: "memory")
#define TC_WAIT_LD() asm volatile("tcgen05.wait::ld.sync.aligned;" ::: "memory")

__device__ __forceinline__ void tc_mma_f16_ss(uint32_t d, uint64_t adesc, uint64_t bdesc,
                                              uint32_t idesc, uint32_t en) {
    asm volatile(
        "{.reg .pred p; setp.ne.u32 p, %5, 0;\n\t"
        "tcgen05.mma.cta_group::1.kind::f16 [%0], %1, %2, %3, {%4, %4, %4, %4}, p;}\n\t"
        :: "r"(d), "l"(adesc), "l"(bdesc), "r"(idesc), "r"(0u), "r"(en) : "memory");
}

#define TC_LD_X32(r, addr) \
    asm volatile( \
        "tcgen05.ld.sync.aligned.32x32b.x32.b32 " \
        "{%0,%1,%2,%3,%4,%5,%6,%7,%8,%9,%10,%11,%12,%13,%14,%15," \
        "%16,%17,%18,%19,%20,%21,%22,%23,%24,%25,%26,%27,%28,%29,%30,%31}, [%32];" \
        : "=r"((r)[0]),"=r"((r)[1]),"=r"((r)[2]),"=r"((r)[3]), \
          "=r"((r)[4]),"=r"((r)[5]),"=r"((r)[6]),"=r"((r)[7]), \
          "=r"((r)[8]),"=r"((r)[9]),"=r"((r)[10]),"=r"((r)[11]), \
          "=r"((r)[12]),"=r"((r)[13]),"=r"((r)[14]),"=r"((r)[15]), \
          "=r"((r)[16]),"=r"((r)[17]),"=r"((r)[18]),"=r"((r)[19]), \
          "=r"((r)[20]),"=r"((r)[21]),"=r"((r)[22]),"=r"((r)[23]), \
          "=r"((r)[24]),"=r"((r)[25]),"=r"((r)[26]),"=r"((r)[27]), \
          "=r"((r)[28]),"=r"((r)[29]),"=r"((r)[30]),"=r"((r)[31]) \
        : "r"(addr))

// SW128 smem descriptor: layout=2, version=1, SBO=64 (1024B per 8-row group), LBO=1
static constexpr uint64_t DESC_BASE_SW128 =
    (uint64_t(2) << 61) | (uint64_t(1) << 46) | (uint64_t(64) << 32) | (uint64_t(1) << 16);
__device__ __forceinline__ uint64_t make_desc(uint32_t addr) {
    return DESC_BASE_SW128 | ((uint64_t)(addr >> 4) & 0x3FFF);
}

static constexpr uint32_t IDESC_F16 = 0x8200490u;  // F32 acc, bf16 x bf16, M=128, N=128

// descriptor offset (16B units) for K-step k of a 128x128 bf16 blocked-SW128 tile
__device__ __forceinline__ uint64_t kofs(int k) {
    return (uint64_t)((k & 3) * 2 + (k >> 2) * 1024);
}

__device__ __forceinline__ void copy_tile(const __nv_bfloat16* __restrict__ src,
                                          char* __restrict__ dst, int tid) {
    const uint4* s4 = reinterpret_cast<const uint4*>(src);
#pragma unroll
    for (int q = tid; q < 2048; q += 256) {
        uint4 v = s4[q];
        int r = q >> 4, c16 = q & 15;
        int boff = ((r >> 3) + ((c16 >> 3) << 4)) * 1024 + (r & 7) * 128 + (c16 & 7) * 16;
        boff ^= ((boff >> 3) & 0x70);
        *reinterpret_cast<uint4*>(dst + boff) = v;
    }
}
#endif  // HAS_TCGEN05

__global__ __launch_bounds__(256, 1)
void k5_tc(const float* __restrict__ hp_unused, float* __restrict__ A) {
#if HAS_TCGEN05
    extern __shared__ char smem[];
    const uint32_t sbase = smem_u32(smem);
    const int tid = threadIdx.x;
    const int wid = tid >> 5, lane = tid & 31;

    const int b    = blockIdx.z;
    const int row0 = blockIdx.y * 128;
    const int cg   = blockIdx.x * COLT;         // first col tile index
    const size_t bofs = (size_t)b * NN * HID;

    if (wid == 0) TC_ALLOC(sbase, 128);
    if (tid == 0) MBAR_INIT(sbase + 8, 1);

    // A tiles (persist) + first B tiles into buf0
    copy_tile(g_th + bofs + (size_t)row0 * HID, smem + SM_AHI, tid);
    copy_tile(g_tl + bofs + (size_t)row0 * HID, smem + SM_ALO, tid);
    copy_tile(g_ph + bofs + (size_t)(cg * 128) * HID, smem + SM_B0H, tid);
    copy_tile(g_pl + bofs + (size_t)(cg * 128) * HID, smem + SM_B0L, tid);
    FENCE_ASYNC_SHARED();
    __syncthreads();

    uint32_t tmem;
    asm volatile("ld.shared.b32 %0, [%1];" : "=r"(tmem) : "r"(sbase));

    const uint64_t dAh = make_desc(sbase + SM_AHI);
    const uint64_t dAl = make_desc(sbase + SM_ALO);
    float* Ab = A + (size_t)b * NN * NN;

    for (int i = 0; i < COLT; i++) {
        const int buf = i & 1;
        const uint32_t bh = buf ? SM_B1H : SM_B0H;
        const uint32_t bl = buf ? SM_B1L : SM_B0L;

        // issue MMA for this col tile
        if (wid == 0) {
            if (i == 0) TC_RELINQ();
            if (elect_one_pred()) {
                const uint64_t dBh = make_desc(sbase + bh);
                const uint64_t dBl = make_desc(sbase + bl);
#pragma unroll
                for (int k = 0; k < 8; k++)
                    tc_mma_f16_ss(tmem, dAh + kofs(k), dBh + kofs(k), IDESC_F16, k > 0);
#pragma unroll
                for (int k = 0; k < 8; k++)
                    tc_mma_f16_ss(tmem, dAh + kofs(k), dBl + kofs(k), IDESC_F16, 1);
#pragma unroll
                for (int k = 0; k < 8; k++)
                    tc_mma_f16_ss(tmem, dAl + kofs(k), dBh + kofs(k), IDESC_F16, 1);
                TC_COMMIT(sbase + 8);
            }
        }

        // overlap: prefetch next B tiles into the other buffer while MMA runs
        if (i + 1 < COLT) {
            const int nbh = (buf ^ 1) ? SM_B1H : SM_B0H;
            const int nbl = (buf ^ 1) ? SM_B1L : SM_B0L;
            const size_t c1 = (size_t)((cg + i + 1) * 128) * HID;
            copy_tile(g_ph + bofs + c1, smem + nbh, tid);
            copy_tile(g_pl + bofs + c1, smem + nbl, tid);
            FENCE_ASYNC_SHARED();
        }

        mbar_wait(sbase + 8, i & 1);
        TC_FENCE_AFTER();

        // epilogue: 8 warps; warp = (sub, half)
        {
            const int sub = wid & 3, half = wid >> 2;
            const int colb = half * 64;
            uint32_t d0[32], d1[32];
            TC_LD_X32(d0, tmem + colb);
            TC_LD_X32(d1, tmem + colb + 32);
            TC_WAIT_LD();

            float* out = Ab + (size_t)(row0 + sub * 32 + lane) * NN
                         + (cg + i) * 128 + colb;
#pragma unroll
            for (int c = 0; c < 32; c += 4) {
                float4 w = make_float4(__uint_as_float(d0[c]), __uint_as_float(d0[c + 1]),
                                       __uint_as_float(d0[c + 2]), __uint_as_float(d0[c + 3]));
                *reinterpret_cast<float4*>(out + c) = w;
            }
#pragma unroll
            for (int c = 0; c < 32; c += 4) {
                float4 w = make_float4(__uint_as_float(d1[c]), __uint_as_float(d1[c + 1]),
                                       __uint_as_float(d1[c + 2]), __uint_as_float(d1[c + 3]));
                *reinterpret_cast<float4*>(out + 32 + c) = w;
            }
        }
        TC_FENCE_BEFORE();
        __syncthreads();   // epilogue LDTM done + next-B STS visible before next MMA
    }

    if (tid == 0) MBAR_INVAL(sbase + 8);
    __syncthreads();
    if (wid == 0) TC_DEALLOC(tmem, 128);
#else
    // SIMT fallback for the compute_103 (non-'a') compile pass. Never runs on
    // sm_103a hardware, but must be correct.
    const int tid = threadIdx.x;
    const int b    = blockIdx.z;
    const int row0 = blockIdx.y * 128;
    const int cg   = blockIdx.x * COLT;
    const size_t bofs = (size_t)b * NN * HID;
    for (int i = 0; i < COLT; i++) {
        const int col0 = (cg + i) * 128;
        for (int e = tid; e < 128 * 128; e += 256) {
            int r = e >> 7, c = e & 127;
            const __nv_bfloat16* th = g_th + bofs + (size_t)(row0 + r) * HID;
            const __nv_bfloat16* tl = g_tl + bofs + (size_t)(row0 + r) * HID;
            const __nv_bfloat16* ph = g_ph + bofs + (size_t)(col0 + c) * HID;
            const __nv_bfloat16* pl = g_pl + bofs + (size_t)(col0 + c) * HID;
            float acc = 0.f;
            for (int k = 0; k < HID; k++) {
                float av = __bfloat162float(th[k]) + __bfloat162float(tl[k]);
                float bv = __bfloat162float(ph[k]) + __bfloat162float(pl[k]);
                acc += av * bv;
            }
            A[(size_t)b * NN * NN + (size_t)(row0 + r) * NN + col0 + c] = acc;
        }
    }
    (void)hp_unused;
#endif
}

// ---------------- launch ----------------
extern "C" void kernel_launch(void* const* d_in, const int* in_sizes, int n_in,
                              void* d_out, int out_size) {
    (void)in_sizes; (void)n_in; (void)out_size;
    const float* x    = (const float*)d_in[0];
    const float* a    = (const float*)d_in[1];
    const float* h    = (const float*)d_in[2];
    const float* kern = (const float*)d_in[3];
    const float* asf  = (const float*)d_in[4];
    const float* anb  = (const float*)d_in[5];
    const float* bias = (const float*)d_in[6];
    const float* bu   = (const float*)d_in[7];
    const float* br   = (const float*)d_in[8];
    const float* bc   = (const float*)d_in[9];
    const float* Wu   = (const float*)d_in[10];
    const float* Wr   = (const float*)d_in[11];
    const float* Wc   = (const float*)d_in[12];
    const float* Rp   = (const float*)d_in[13];

    float* A  = (float*)d_out;                       // [B,N,N]
    float* hp = A + (size_t)BQ * NN * NN;            // [B,N,HID]

    static bool attr_set = false;
    if (!attr_set) {
        cudaFuncSetAttribute(k5_tc, cudaFuncAttributeMaxDynamicSharedMemorySize, SM_TOTAL_K5);
        attr_set = true;
    }

    k1_project <<< (BQ * NN) / 8, 128 >>> (x, kern, asf, anb);
    k2_attention <<< BQ * NN, 128 >>> (a, bias);
    k3_gates <<< (BQ * NN) / 16, 512 >>> (h, bu, br, bc, Wu, Wr, Wc, Rp, hp);
    dim3 g5(NN / 128 / COLT, NN / 128, BQ);
    k5_tc <<< g5, 256, SM_TOTAL_K5 >>> (hp, A);
}